// round 2
// baseline (speedup 1.0000x reference)
#include <cuda_runtime.h>
#include <math.h>

#define BATCH 8
#define SEQ   4096
#define DM    65
#define DH    64
#define BM    64
#define BN    64

// Scratch (allocation-free rule: __device__ globals, referenced directly by kernels)
__device__ float g_qT[BATCH * DH * SEQ];   // [B][64][L], pre-scaled by 1/sqrt(65)
__device__ float g_kT[BATCH * DH * SEQ];   // [B][64][L]
__device__ float g_v [BATCH * SEQ * DH];   // [B][L][64]

// ---------------------------------------------------------------------------
// Projection: out = (x @ W + b) [* scale] ; MODE 0 -> g_qT (scaled, transposed)
//                                           MODE 1 -> g_kT (transposed)
//                                           MODE 2 -> g_v  (row-major)
// ---------------------------------------------------------------------------
template <int MODE>
__global__ void __launch_bounds__(256) proj_kernel(
    const float* __restrict__ x, const float* __restrict__ W,
    const float* __restrict__ bias)
{
    __shared__ float sW[DM * DH];       // 65*64 floats
    __shared__ float sx[4][DM + 1];

    const int tid  = threadIdx.x;
    const int row0 = blockIdx.x * 4;

    for (int f = tid; f < DM * DH; f += 256) sW[f] = W[f];
    for (int f = tid; f < 4 * DM; f += 256) {
        int r = f / DM, d = f % DM;
        sx[r][d] = x[(row0 + r) * DM + d];
    }
    __syncthreads();

    const int r   = tid >> 6;   // 0..3
    const int col = tid & 63;   // 0..63
    float acc = bias[col];
    #pragma unroll
    for (int d = 0; d < DM; d++)
        acc = fmaf(sx[r][d], sW[d * DH + col], acc);

    const int row = row0 + r;
    const int b = row >> 12;        // row / 4096
    const int l = row & 4095;
    if (MODE == 0) {
        g_qT[(size_t)(b * DH + col) * SEQ + l] = acc * 0.12403473458920847f; // 1/sqrt(65)
    } else if (MODE == 1) {
        g_kT[(size_t)(b * DH + col) * SEQ + l] = acc;
    } else {
        g_v[(size_t)row * DH + col] = acc;
    }
}

// ---------------------------------------------------------------------------
// Causal flash attention, fp32. One block = 64 queries of one batch.
// Threads: 256 = 16x16; each thread owns a 4x4 micro-tile.
// SMEM 48KB total: sQt[64*64] | sKP[64*64] (K tile, later aliased as P^T) | sV[64*64]
// ---------------------------------------------------------------------------
#define FLASH_SMEM_BYTES (3 * 64 * 64 * 4)   // 49152 = default dynamic limit

__global__ void __launch_bounds__(256, 3) flash_kernel(float* __restrict__ out)
{
    extern __shared__ float sm[];
    float* sQt = sm;           // [d][i]  stride 64
    float* sKP = sm + 4096;    // [d][j] as K^T, then reused as P^T [j][i] (swizzled)
    float* sV  = sm + 8192;    // [j][c]  stride 64

    const int tid = threadIdx.x;
    const int ty  = tid >> 4;         // 0..15 -> query rows ty*4..ty*4+3
    const int tx  = tid & 15;         // 0..15 -> cols      tx*4..tx*4+3
    const int qt  = 63 - blockIdx.x;  // heavy tiles scheduled first
    const int b   = blockIdx.y;
    const int q0  = qt * BM;
    const int ty4 = ty * 4;

    // Load Q tile (already transposed + scaled in GMEM): coalesced, conflict-free
    for (int f = tid; f < 64 * 16; f += 256) {
        const int d = f >> 4, j4 = f & 15;
        *(float4*)&sQt[d * 64 + j4 * 4] =
            *(const float4*)&g_qT[(size_t)(b * DH + d) * SEQ + q0 + j4 * 4];
    }

    float acc[4][4];
    float m_i[4], l_i[4];
    #pragma unroll
    for (int r = 0; r < 4; r++) {
        m_i[r] = -1e30f; l_i[r] = 0.f;
        #pragma unroll
        for (int c = 0; c < 4; c++) acc[r][c] = 0.f;
    }

    for (int kt = 0; kt <= qt; kt++) {
        const int k0 = kt * BN;

        __syncthreads();  // prev iteration's readers of sKP/sV done
        for (int f = tid; f < 64 * 16; f += 256) {
            const int d = f >> 4, j4 = f & 15;
            *(float4*)&sKP[d * 64 + j4 * 4] =
                *(const float4*)&g_kT[(size_t)(b * DH + d) * SEQ + k0 + j4 * 4];
        }
        for (int f = tid; f < 64 * 16; f += 256) {
            const int j = f >> 4, c4 = f & 15;
            *(float4*)&sV[j * 64 + c4 * 4] =
                *(const float4*)&g_v[((size_t)b * SEQ + k0 + j) * DH + c4 * 4];
        }
        __syncthreads();

        // ---- S = Q K^T (scale folded into Q) ----
        float s[4][4];
        #pragma unroll
        for (int r = 0; r < 4; r++)
            #pragma unroll
            for (int c = 0; c < 4; c++) s[r][c] = 0.f;

        #pragma unroll 8
        for (int d = 0; d < 64; d++) {
            const float4 q4 = *(const float4*)&sQt[d * 64 + ty4];
            const float4 k4 = *(const float4*)&sKP[d * 64 + tx * 4];
            float qr[4] = {q4.x, q4.y, q4.z, q4.w};
            float kc[4] = {k4.x, k4.y, k4.z, k4.w};
            #pragma unroll
            for (int r = 0; r < 4; r++)
                #pragma unroll
                for (int c = 0; c < 4; c++)
                    s[r][c] = fmaf(qr[r], kc[c], s[r][c]);
        }

        // ---- causal mask on diagonal tile ----
        if (kt == qt) {
            #pragma unroll
            for (int r = 0; r < 4; r++)
                #pragma unroll
                for (int c = 0; c < 4; c++)
                    if (tx * 4 + c > ty4 + r) s[r][c] = -1e30f;
        }

        // ---- online softmax (register state, 16-lane shuffles) ----
        #pragma unroll
        for (int r = 0; r < 4; r++) {
            float mt = fmaxf(fmaxf(s[r][0], s[r][1]), fmaxf(s[r][2], s[r][3]));
            #pragma unroll
            for (int off = 8; off >= 1; off >>= 1)
                mt = fmaxf(mt, __shfl_xor_sync(0xffffffffu, mt, off));
            const float mnew  = fmaxf(m_i[r], mt);
            const float alpha = __expf(m_i[r] - mnew);
            m_i[r] = mnew;
            float ls = 0.f;
            #pragma unroll
            for (int c = 0; c < 4; c++) {
                s[r][c] = __expf(s[r][c] - mnew);
                ls += s[r][c];
            }
            #pragma unroll
            for (int off = 8; off >= 1; off >>= 1)
                ls += __shfl_xor_sync(0xffffffffu, ls, off);
            l_i[r] = l_i[r] * alpha + ls;
            #pragma unroll
            for (int c = 0; c < 4; c++) acc[r][c] *= alpha;
        }

        __syncthreads();  // everyone done reading sKP as K before we overwrite as P^T

        // ---- write P transposed into sKP with XOR swizzle (STS.128) ----
        #pragma unroll
        for (int c = 0; c < 4; c++) {
            const int row = tx * 4 + c;
            *(float4*)&sKP[row * 64 + (ty4 ^ (row & 28))] =
                make_float4(s[0][c], s[1][c], s[2][c], s[3][c]);
        }
        __syncthreads();

        // ---- O += P V ----
        #pragma unroll 8
        for (int j = 0; j < 64; j++) {
            const float4 p4 = *(const float4*)&sKP[j * 64 + (ty4 ^ (j & 28))];
            const float4 v4 = *(const float4*)&sV[j * 64 + tx * 4];
            float pr[4] = {p4.x, p4.y, p4.z, p4.w};
            float vc[4] = {v4.x, v4.y, v4.z, v4.w};
            #pragma unroll
            for (int r = 0; r < 4; r++)
                #pragma unroll
                for (int c = 0; c < 4; c++)
                    acc[r][c] = fmaf(pr[r], vc[c], acc[r][c]);
        }
    }

    // ---- epilogue: normalize and store (coalesced float4) ----
    #pragma unroll
    for (int r = 0; r < 4; r++) {
        const float inv = 1.f / l_i[r];
        *(float4*)&out[((size_t)b * SEQ + q0 + ty4 + r) * DH + tx * 4] =
            make_float4(acc[r][0] * inv, acc[r][1] * inv,
                        acc[r][2] * inv, acc[r][3] * inv);
    }
}

// ---------------------------------------------------------------------------
extern "C" void kernel_launch(void* const* d_in, const int* in_sizes, int n_in,
                              void* d_out, int out_size)
{
    const float* x  = (const float*)d_in[0];
    const float* Wq = (const float*)d_in[1];
    const float* bq = (const float*)d_in[2];
    const float* Wk = (const float*)d_in[3];
    const float* bk = (const float*)d_in[4];
    const float* Wv = (const float*)d_in[5];
    const float* bv = (const float*)d_in[6];
    float* out = (float*)d_out;

    const int pblocks = (BATCH * SEQ) / 4;  // 8192
    proj_kernel<0><<<pblocks, 256>>>(x, Wq, bq);
    proj_kernel<1><<<pblocks, 256>>>(x, Wk, bk);
    proj_kernel<2><<<pblocks, 256>>>(x, Wv, bv);

    dim3 fgrid(SEQ / BM, BATCH);  // (64, 8)
    flash_kernel<<<fgrid, 256, FLASH_SMEM_BYTES>>>(out);
}